// round 1
// baseline (speedup 1.0000x reference)
#include <cuda_runtime.h>

#define NQ 2048
#define NK 4096
#define DIMK 1024
#define PROJ_N 256   // 2*H*D_I

// Scratch for projected Q/K (allocation-free rule: __device__ globals)
__device__ float g_Qp[NQ * PROJ_N];
__device__ float g_Kp[NK * PROJ_N];

// ---------------------------------------------------------------------------
// Projection: C[M, 256] = A[M, 1024] @ W[256, 1024]^T   (both row-major, TN)
// CTA tile 64(M) x 128(N), 256 threads, 4x8 micro-tile, K-chunk 16.
// ---------------------------------------------------------------------------
__global__ __launch_bounds__(256) void proj_kernel(
    const float* __restrict__ A, const float* __restrict__ W, int which)
{
    float* __restrict__ C = which ? g_Kp : g_Qp;
    __shared__ float As[16][68];    // transposed: As[kk][row]
    __shared__ float Ws[16][132];   // transposed: Ws[kk][col]

    const int tid = threadIdx.x;
    const int m0 = blockIdx.x * 64;
    const int n0 = blockIdx.y * 128;
    const int ti = (tid & 15) * 4;   // row offset in tile
    const int tj = (tid >> 4) * 8;   // col offset in tile

    float acc[4][8];
#pragma unroll
    for (int i = 0; i < 4; i++)
#pragma unroll
        for (int j = 0; j < 8; j++) acc[i][j] = 0.f;

    for (int kk0 = 0; kk0 < DIMK; kk0 += 16) {
        // Load A chunk: 64 rows x 16 k = 256 float4, 1 per thread, transpose.
        {
            int r = tid & 63, c = tid >> 6;   // c in 0..3
            float4 v = *(const float4*)(A + (size_t)(m0 + r) * DIMK + kk0 + c * 4);
            As[c*4+0][r] = v.x; As[c*4+1][r] = v.y;
            As[c*4+2][r] = v.z; As[c*4+3][r] = v.w;
        }
        // Load W chunk: 128 rows x 16 k = 512 float4, 2 per thread, transpose.
#pragma unroll
        for (int s = 0; s < 2; s++) {
            int f = tid + 256 * s;
            int r = f & 127, c = f >> 7;      // c in 0..3
            float4 v = *(const float4*)(W + (size_t)(n0 + r) * DIMK + kk0 + c * 4);
            Ws[c*4+0][r] = v.x; Ws[c*4+1][r] = v.y;
            Ws[c*4+2][r] = v.z; Ws[c*4+3][r] = v.w;
        }
        __syncthreads();
#pragma unroll
        for (int kk = 0; kk < 16; kk++) {
            float4 a  = *(const float4*)&As[kk][ti];
            float4 b0 = *(const float4*)&Ws[kk][tj];
            float4 b1 = *(const float4*)&Ws[kk][tj + 4];
            float av[4] = {a.x, a.y, a.z, a.w};
            float bv[8] = {b0.x, b0.y, b0.z, b0.w, b1.x, b1.y, b1.z, b1.w};
#pragma unroll
            for (int i = 0; i < 4; i++)
#pragma unroll
                for (int j = 0; j < 8; j++)
                    acc[i][j] = fmaf(av[i], bv[j], acc[i][j]);
        }
        __syncthreads();
    }

#pragma unroll
    for (int i = 0; i < 4; i++) {
        float* Cp = C + (size_t)(m0 + ti + i) * PROJ_N + n0 + tj;
        *(float4*)(Cp)     = make_float4(acc[i][0], acc[i][1], acc[i][2], acc[i][3]);
        *(float4*)(Cp + 4) = make_float4(acc[i][4], acc[i][5], acc[i][6], acc[i][7]);
    }
}

// ---------------------------------------------------------------------------
// Main: per (q,k) compute 8 head-dots (D=32 each), then RPE + gate MLP epilogue.
// CTA tile 64q x 64k, 256 threads, 4x4 micro-tile, 8 accumulators per element.
// ---------------------------------------------------------------------------
__global__ __launch_bounds__(256, 1) void rpe_gate_kernel(
    const int*   __restrict__ qpos, const int* __restrict__ kpos,
    const float* __restrict__ rpe_table,
    const float* __restrict__ w1, const float* __restrict__ b1,
    const float* __restrict__ w2, const float* __restrict__ b2,
    float* __restrict__ out)
{
    __shared__ float  Qs[32][68];   // Qs[kk][q_row]
    __shared__ float  Ks[32][68];   // Ks[kk][k_row]
    __shared__ float4 rpe_s[257];

    const int tid = threadIdx.x;
    const int q0 = blockIdx.y * 64;
    const int k0 = blockIdx.x * 64;

    for (int i = tid; i < 257; i += 256)
        rpe_s[i] = ((const float4*)rpe_table)[i];

    const int ti = (tid & 15) * 4;   // q offset in tile
    const int tj = (tid >> 4) * 4;   // k offset in tile

    float acc[8][4][4];
#pragma unroll
    for (int h = 0; h < 8; h++)
#pragma unroll
        for (int i = 0; i < 4; i++)
#pragma unroll
            for (int j = 0; j < 4; j++) acc[h][i][j] = 0.f;

#pragma unroll
    for (int h = 0; h < 8; h++) {
        // Load 64x32 chunks of Qp and Kp (head h columns), transpose into smem.
#pragma unroll
        for (int s = 0; s < 2; s++) {
            int f = tid + 256 * s;
            int r = f & 63, c = f >> 6;   // c in 0..7
            float4 vq = *(const float4*)(g_Qp + (size_t)(q0 + r) * PROJ_N + h * 32 + c * 4);
            Qs[c*4+0][r] = vq.x; Qs[c*4+1][r] = vq.y;
            Qs[c*4+2][r] = vq.z; Qs[c*4+3][r] = vq.w;
            float4 vk = *(const float4*)(g_Kp + (size_t)(k0 + r) * PROJ_N + h * 32 + c * 4);
            Ks[c*4+0][r] = vk.x; Ks[c*4+1][r] = vk.y;
            Ks[c*4+2][r] = vk.z; Ks[c*4+3][r] = vk.w;
        }
        __syncthreads();
#pragma unroll 8
        for (int kk = 0; kk < 32; kk++) {
            float4 a = *(const float4*)&Qs[kk][ti];
            float4 b = *(const float4*)&Ks[kk][tj];
            float av[4] = {a.x, a.y, a.z, a.w};
            float bv[4] = {b.x, b.y, b.z, b.w};
#pragma unroll
            for (int i = 0; i < 4; i++)
#pragma unroll
                for (int j = 0; j < 4; j++)
                    acc[h][i][j] = fmaf(av[i], bv[j], acc[h][i][j]);
        }
        __syncthreads();
    }

    // ---- Epilogue: RPE add, relu, 4->8->4 gate MLP, sigmoid, weighted sum ----
    float w1r[8][4], b1r[8], w2r[4][8], b2r[4];
#pragma unroll
    for (int e = 0; e < 8; e++) {
        b1r[e] = __ldg(&b1[e]);
#pragma unroll
        for (int h = 0; h < 4; h++) w1r[e][h] = __ldg(&w1[e * 4 + h]);
    }
#pragma unroll
    for (int h = 0; h < 4; h++) {
        b2r[h] = __ldg(&b2[h]);
#pragma unroll
        for (int e = 0; e < 8; e++) w2r[h][e] = __ldg(&w2[h * 8 + e]);
    }

    int qp[4], kp[4];
#pragma unroll
    for (int i = 0; i < 4; i++) qp[i] = __ldg(&qpos[q0 + ti + i]);
#pragma unroll
    for (int j = 0; j < 4; j++) kp[j] = __ldg(&kpos[k0 + tj + j]);

#pragma unroll
    for (int i = 0; i < 4; i++) {
        float rj[4];
#pragma unroll
        for (int j = 0; j < 4; j++) {
            int rel = qp[i] - kp[j];
            rel = rel < -128 ? -128 : (rel > 128 ? 128 : rel);
            float4 rp = rpe_s[rel + 128];
            float rph[4] = {rp.x, rp.y, rp.z, rp.w};

            float sh[4], gh[4];
#pragma unroll
            for (int h = 0; h < 4; h++) {
                sh[h] = fmaxf(acc[h][i][j] + rph[h], 0.f);
                gh[h] = acc[4 + h][i][j] + rph[h];
            }

            float zh[4] = {b2r[0], b2r[1], b2r[2], b2r[3]};
#pragma unroll
            for (int e = 0; e < 8; e++) {
                float t = b1r[e];
#pragma unroll
                for (int h = 0; h < 4; h++) t = fmaf(gh[h], w1r[e][h], t);
                t = fmaxf(t, 0.f);
#pragma unroll
                for (int h = 0; h < 4; h++) zh[h] = fmaf(t, w2r[h][e], zh[h]);
            }

            float o = 0.f;
#pragma unroll
            for (int h = 0; h < 4; h++) {
                float g = __fdividef(1.f, 1.f + __expf(-zh[h]));
                o = fmaf(sh[h], g, o);
            }
            rj[j] = o;
        }
        *(float4*)(out + (size_t)(q0 + ti + i) * NK + k0 + tj) =
            make_float4(rj[0], rj[1], rj[2], rj[3]);
    }
}

// ---------------------------------------------------------------------------
extern "C" void kernel_launch(void* const* d_in, const int* in_sizes, int n_in,
                              void* d_out, int out_size)
{
    const float* query = (const float*)d_in[0];
    const float* key   = (const float*)d_in[1];
    const int*   qpos  = (const int*)  d_in[2];
    const int*   kpos  = (const int*)  d_in[3];
    const float* Wq    = (const float*)d_in[4];
    const float* Wk    = (const float*)d_in[5];
    const float* rpe   = (const float*)d_in[6];
    const float* w1    = (const float*)d_in[7];
    const float* b1    = (const float*)d_in[8];
    const float* w2    = (const float*)d_in[9];
    const float* b2    = (const float*)d_in[10];
    float* out = (float*)d_out;
    (void)in_sizes; (void)n_in; (void)out_size;

    proj_kernel<<<dim3(NQ / 64, 2), 256>>>(query, Wq, 0);
    proj_kernel<<<dim3(NK / 64, 2), 256>>>(key,   Wk, 1);
    rpe_gate_kernel<<<dim3(NK / 64, NQ / 64), 256>>>(
        qpos, kpos, rpe, w1, b1, w2, b2, out);
}

// round 3
// speedup vs baseline: 1.2098x; 1.2098x over previous
#include <cuda_runtime.h>

#define NQ 2048
#define NK 4096
#define DIMK 1024
#define PROJ_N 256   // 2*H*D_I

// Scratch for projected Q/K (allocation-free rule: __device__ globals)
__device__ float g_Qp[NQ * PROJ_N];
__device__ float g_Kp[NK * PROJ_N];

// ---------------------------------------------------------------------------
// Fused projection: C[M,256] = A[M,1024] @ W[256,1024]^T  for Q and K in one
// launch. 64x64 tiles, 256 threads, 4x4 micro-tile, K-chunk 16, double-
// buffered smem with gmem prefetch. Grid = 128 (Q tiles) + 256 (K tiles).
// ---------------------------------------------------------------------------
__global__ __launch_bounds__(256, 3) void proj_fused(
    const float* __restrict__ Qin, const float* __restrict__ Kin,
    const float* __restrict__ Wq,  const float* __restrict__ Wk)
{
    __shared__ float As[2][16][68];   // As[buf][kk][row]
    __shared__ float Ws[2][16][68];   // Ws[buf][kk][col]

    int b = blockIdx.x;
    const float *A, *W;
    float* C;
    if (b < 128) { A = Qin; W = Wq; C = g_Qp; }
    else         { b -= 128; A = Kin; W = Wk; C = g_Kp; }
    const int m0 = (b >> 2) * 64;
    const int n0 = (b & 3) * 64;

    const int tid = threadIdx.x;
    const int ti = (tid & 15) * 4;
    const int tj = (tid >> 4) * 4;
    const int lr = tid & 63;          // load row within tile
    const int lc = tid >> 6;          // load k-group 0..3

    const float* Ap = A + (size_t)(m0 + lr) * DIMK + lc * 4;
    const float* Wp = W + (size_t)(n0 + lr) * DIMK + lc * 4;

    // preload chunk 0
    {
        float4 va = *(const float4*)Ap;
        float4 vw = *(const float4*)Wp;
        As[0][lc*4+0][lr] = va.x; As[0][lc*4+1][lr] = va.y;
        As[0][lc*4+2][lr] = va.z; As[0][lc*4+3][lr] = va.w;
        Ws[0][lc*4+0][lr] = vw.x; Ws[0][lc*4+1][lr] = vw.y;
        Ws[0][lc*4+2][lr] = vw.z; Ws[0][lc*4+3][lr] = vw.w;
    }
    Ap += 16; Wp += 16;
    __syncthreads();

    float acc[4][4];
#pragma unroll
    for (int i = 0; i < 4; i++)
#pragma unroll
        for (int j = 0; j < 4; j++) acc[i][j] = 0.f;

    for (int ch = 0; ch < 64; ch++) {
        const int p = ch & 1;
        float4 na, nw;
        if (ch < 63) {
            na = *(const float4*)Ap;
            nw = *(const float4*)Wp;
            Ap += 16; Wp += 16;
        }
#pragma unroll
        for (int kk = 0; kk < 16; kk++) {
            float4 a = *(const float4*)&As[p][kk][ti];
            float4 w = *(const float4*)&Ws[p][kk][tj];
            float av[4] = {a.x, a.y, a.z, a.w};
            float wv[4] = {w.x, w.y, w.z, w.w};
#pragma unroll
            for (int i = 0; i < 4; i++)
#pragma unroll
                for (int j = 0; j < 4; j++)
                    acc[i][j] = fmaf(av[i], wv[j], acc[i][j]);
        }
        if (ch < 63) {
            const int q = 1 - p;
            As[q][lc*4+0][lr] = na.x; As[q][lc*4+1][lr] = na.y;
            As[q][lc*4+2][lr] = na.z; As[q][lc*4+3][lr] = na.w;
            Ws[q][lc*4+0][lr] = nw.x; Ws[q][lc*4+1][lr] = nw.y;
            Ws[q][lc*4+2][lr] = nw.z; Ws[q][lc*4+3][lr] = nw.w;
            __syncthreads();
        }
    }

#pragma unroll
    for (int i = 0; i < 4; i++) {
        *(float4*)(C + (size_t)(m0 + ti + i) * PROJ_N + n0 + tj) =
            make_float4(acc[i][0], acc[i][1], acc[i][2], acc[i][3]);
    }
}

// ---------------------------------------------------------------------------
// Main: per (q,k) compute 8 head-dots (D=32 each), then RPE + gate MLP.
// CTA tile 64q x 64k, 256 threads, 4x4 micro-tile, 8 head accumulators.
// Head tiles double-buffered in smem, gmem prefetch of head h+1 overlaps
// compute of head h; one barrier per head.
// ---------------------------------------------------------------------------
__global__ __launch_bounds__(256, 1) void rpe_gate_kernel(
    const int*   __restrict__ qpos, const int* __restrict__ kpos,
    const float* __restrict__ rpe_table,
    const float* __restrict__ w1, const float* __restrict__ b1,
    const float* __restrict__ w2, const float* __restrict__ b2,
    float* __restrict__ out)
{
    __shared__ float  Qs[2][32][68];   // Qs[buf][kk][q_row]
    __shared__ float  Ks[2][32][68];   // Ks[buf][kk][k_row]
    __shared__ float4 rpe_s[257];

    const int tid = threadIdx.x;
    const int q0 = blockIdx.y * 64;
    const int k0 = blockIdx.x * 64;

    for (int i = tid; i < 257; i += 256)
        rpe_s[i] = ((const float4*)rpe_table)[i];

    const int ti = (tid & 15) * 4;     // q offset in tile
    const int tj = (tid >> 4) * 4;     // k offset in tile
    const int lr = tid & 63;           // load row
    const int lc0 = tid >> 6;          // k-group for s=0 (0..3); s=1 -> +4

    const float* Qb = g_Qp + (size_t)(q0 + lr) * PROJ_N;
    const float* Kb = g_Kp + (size_t)(k0 + lr) * PROJ_N;

    float acc[8][4][4];
#pragma unroll
    for (int h = 0; h < 8; h++)
#pragma unroll
        for (int i = 0; i < 4; i++)
#pragma unroll
            for (int j = 0; j < 4; j++) acc[h][i][j] = 0.f;

    // preload head 0
    {
        float4 vq0 = *(const float4*)(Qb + lc0 * 4);
        float4 vq1 = *(const float4*)(Qb + (lc0 + 4) * 4);
        float4 vk0 = *(const float4*)(Kb + lc0 * 4);
        float4 vk1 = *(const float4*)(Kb + (lc0 + 4) * 4);
        Qs[0][lc0*4+0][lr]  = vq0.x; Qs[0][lc0*4+1][lr]  = vq0.y;
        Qs[0][lc0*4+2][lr]  = vq0.z; Qs[0][lc0*4+3][lr]  = vq0.w;
        Qs[0][lc0*4+16][lr] = vq1.x; Qs[0][lc0*4+17][lr] = vq1.y;
        Qs[0][lc0*4+18][lr] = vq1.z; Qs[0][lc0*4+19][lr] = vq1.w;
        Ks[0][lc0*4+0][lr]  = vk0.x; Ks[0][lc0*4+1][lr]  = vk0.y;
        Ks[0][lc0*4+2][lr]  = vk0.z; Ks[0][lc0*4+3][lr]  = vk0.w;
        Ks[0][lc0*4+16][lr] = vk1.x; Ks[0][lc0*4+17][lr] = vk1.y;
        Ks[0][lc0*4+18][lr] = vk1.z; Ks[0][lc0*4+19][lr] = vk1.w;
    }
    __syncthreads();

#pragma unroll
    for (int h = 0; h < 8; h++) {
        const int p = h & 1;
        float4 nq0, nq1, nk0, nk1;
        if (h < 7) {
            const float* Qh = Qb + (h + 1) * 32;
            const float* Kh = Kb + (h + 1) * 32;
            nq0 = *(const float4*)(Qh + lc0 * 4);
            nq1 = *(const float4*)(Qh + (lc0 + 4) * 4);
            nk0 = *(const float4*)(Kh + lc0 * 4);
            nk1 = *(const float4*)(Kh + (lc0 + 4) * 4);
        }
#pragma unroll 8
        for (int kk = 0; kk < 32; kk++) {
            float4 a = *(const float4*)&Qs[p][kk][ti];
            float4 bv4 = *(const float4*)&Ks[p][kk][tj];
            float av[4] = {a.x, a.y, a.z, a.w};
            float bv[4] = {bv4.x, bv4.y, bv4.z, bv4.w};
#pragma unroll
            for (int i = 0; i < 4; i++)
#pragma unroll
                for (int j = 0; j < 4; j++)
                    acc[h][i][j] = fmaf(av[i], bv[j], acc[h][i][j]);
        }
        if (h < 7) {
            const int q = 1 - p;
            Qs[q][lc0*4+0][lr]  = nq0.x; Qs[q][lc0*4+1][lr]  = nq0.y;
            Qs[q][lc0*4+2][lr]  = nq0.z; Qs[q][lc0*4+3][lr]  = nq0.w;
            Qs[q][lc0*4+16][lr] = nq1.x; Qs[q][lc0*4+17][lr] = nq1.y;
            Qs[q][lc0*4+18][lr] = nq1.z; Qs[q][lc0*4+19][lr] = nq1.w;
            Ks[q][lc0*4+0][lr]  = nk0.x; Ks[q][lc0*4+1][lr]  = nk0.y;
            Ks[q][lc0*4+2][lr]  = nk0.z; Ks[q][lc0*4+3][lr]  = nk0.w;
            Ks[q][lc0*4+16][lr] = nk1.x; Ks[q][lc0*4+17][lr] = nk1.y;
            Ks[q][lc0*4+18][lr] = nk1.z; Ks[q][lc0*4+19][lr] = nk1.w;
            __syncthreads();
        }
    }

    // ---- Epilogue: RPE add, relu, 4->8->4 gate MLP, sigmoid, weighted sum ----
    float w1r[8][4], b1r[8], w2r[4][8], b2r[4];
#pragma unroll
    for (int e = 0; e < 8; e++) {
        b1r[e] = __ldg(&b1[e]);
#pragma unroll
        for (int h = 0; h < 4; h++) w1r[e][h] = __ldg(&w1[e * 4 + h]);
    }
#pragma unroll
    for (int h = 0; h < 4; h++) {
        b2r[h] = __ldg(&b2[h]);
#pragma unroll
        for (int e = 0; e < 8; e++) w2r[h][e] = __ldg(&w2[h * 8 + e]);
    }

    int qp[4], kp[4];
#pragma unroll
    for (int i = 0; i < 4; i++) qp[i] = __ldg(&qpos[q0 + ti + i]);
#pragma unroll
    for (int j = 0; j < 4; j++) kp[j] = __ldg(&kpos[k0 + tj + j]);

#pragma unroll
    for (int i = 0; i < 4; i++) {
        float rj[4];
#pragma unroll
        for (int j = 0; j < 4; j++) {
            int rel = qp[i] - kp[j];
            rel = rel < -128 ? -128 : (rel > 128 ? 128 : rel);
            float4 rp = rpe_s[rel + 128];
            float rph[4] = {rp.x, rp.y, rp.z, rp.w};

            float sh[4], gh[4];
#pragma unroll
            for (int h = 0; h < 4; h++) {
                sh[h] = fmaxf(acc[h][i][j] + rph[h], 0.f);
                gh[h] = acc[4 + h][i][j] + rph[h];
            }

            float zh[4] = {b2r[0], b2r[1], b2r[2], b2r[3]};
#pragma unroll
            for (int e = 0; e < 8; e++) {
                float t = b1r[e];
#pragma unroll
                for (int h = 0; h < 4; h++) t = fmaf(gh[h], w1r[e][h], t);
                t = fmaxf(t, 0.f);
#pragma unroll
                for (int h = 0; h < 4; h++) zh[h] = fmaf(t, w2r[h][e], zh[h]);
            }

            float o = 0.f;
#pragma unroll
            for (int h = 0; h < 4; h++) {
                float g = __fdividef(1.f, 1.f + __expf(-zh[h]));
                o = fmaf(sh[h], g, o);
            }
            rj[j] = o;
        }
        *(float4*)(out + (size_t)(q0 + ti + i) * NK + k0 + tj) =
            make_float4(rj[0], rj[1], rj[2], rj[3]);
    }
}

// ---------------------------------------------------------------------------
extern "C" void kernel_launch(void* const* d_in, const int* in_sizes, int n_in,
                              void* d_out, int out_size)
{
    const float* query = (const float*)d_in[0];
    const float* key   = (const float*)d_in[1];
    const int*   qpos  = (const int*)  d_in[2];
    const int*   kpos  = (const int*)  d_in[3];
    const float* Wq    = (const float*)d_in[4];
    const float* Wk    = (const float*)d_in[5];
    const float* rpe   = (const float*)d_in[6];
    const float* w1    = (const float*)d_in[7];
    const float* b1    = (const float*)d_in[8];
    const float* w2    = (const float*)d_in[9];
    const float* b2    = (const float*)d_in[10];
    float* out = (float*)d_out;
    (void)in_sizes; (void)n_in; (void)out_size;

    proj_fused<<<384, 256>>>(query, key, Wq, Wk);
    rpe_gate_kernel<<<dim3(NK / 64, NQ / 64), 256>>>(
        qpos, kpos, rpe, w1, b1, w2, b2, out);
}

// round 5
// speedup vs baseline: 2.0066x; 1.6587x over previous
#include <cuda_runtime.h>
#include <cuda_bf16.h>
#include <cstdint>

#define NQ 2048
#define NK 4096
#define DIMK 1024
#define PROJ_N 256   // 2*H*D_I

// Split-bf16 operand storage: per (pos, head) one 128B row = hi d0..31 | lo d0..31,
// 16B units permuted u ^= (pos & 7)  (conflict-free ldmatrix).
// K: 4096 pos x 8 heads x 128B = 4MB.  Q: 2048 x 8 x 128B = 2MB.
__device__ uint4 g_K_sw[NK * 8 * 8];   // (pos*8+head)*8 units
__device__ uint4 g_Q_sw[NQ * 8 * 8];

// ---------------------------------------------------------------------------
// Fused projection (fp32 SIMT, known good) -> bf16-split swizzled layout.
// ---------------------------------------------------------------------------
__global__ __launch_bounds__(256, 3) void proj_fused(
    const float* __restrict__ Qin, const float* __restrict__ Kin,
    const float* __restrict__ Wq,  const float* __restrict__ Wk)
{
    __shared__ float As[2][16][68];
    __shared__ float Ws[2][16][68];

    int b = blockIdx.x;
    const float *A, *W;
    int isQ;
    if (b < 128) { A = Qin; W = Wq; isQ = 1; }
    else         { b -= 128; A = Kin; W = Wk; isQ = 0; }
    const int m0 = (b >> 2) * 64;
    const int n0 = (b & 3) * 64;

    const int tid = threadIdx.x;
    const int ti = (tid & 15) * 4;
    const int tj = (tid >> 4) * 4;
    const int lr = tid & 63;
    const int lc = tid >> 6;

    const float* Ap = A + (size_t)(m0 + lr) * DIMK + lc * 4;
    const float* Wp = W + (size_t)(n0 + lr) * DIMK + lc * 4;

    {
        float4 va = *(const float4*)Ap;
        float4 vw = *(const float4*)Wp;
        As[0][lc*4+0][lr] = va.x; As[0][lc*4+1][lr] = va.y;
        As[0][lc*4+2][lr] = va.z; As[0][lc*4+3][lr] = va.w;
        Ws[0][lc*4+0][lr] = vw.x; Ws[0][lc*4+1][lr] = vw.y;
        Ws[0][lc*4+2][lr] = vw.z; Ws[0][lc*4+3][lr] = vw.w;
    }
    Ap += 16; Wp += 16;
    __syncthreads();

    float acc[4][4];
#pragma unroll
    for (int i = 0; i < 4; i++)
#pragma unroll
        for (int j = 0; j < 4; j++) acc[i][j] = 0.f;

    for (int ch = 0; ch < 64; ch++) {
        const int p = ch & 1;
        float4 na, nw;
        if (ch < 63) {
            na = *(const float4*)Ap;
            nw = *(const float4*)Wp;
            Ap += 16; Wp += 16;
        }
#pragma unroll
        for (int kk = 0; kk < 16; kk++) {
            float4 a = *(const float4*)&As[p][kk][ti];
            float4 w = *(const float4*)&Ws[p][kk][tj];
            float av[4] = {a.x, a.y, a.z, a.w};
            float wv[4] = {w.x, w.y, w.z, w.w};
#pragma unroll
            for (int i = 0; i < 4; i++)
#pragma unroll
                for (int j = 0; j < 4; j++)
                    acc[i][j] = fmaf(av[i], wv[j], acc[i][j]);
        }
        if (ch < 63) {
            const int q = 1 - p;
            As[q][lc*4+0][lr] = na.x; As[q][lc*4+1][lr] = na.y;
            As[q][lc*4+2][lr] = na.z; As[q][lc*4+3][lr] = na.w;
            Ws[q][lc*4+0][lr] = nw.x; Ws[q][lc*4+1][lr] = nw.y;
            Ws[q][lc*4+2][lr] = nw.z; Ws[q][lc*4+3][lr] = nw.w;
            __syncthreads();
        }
    }

    // Epilogue: bf16 split, write swizzled (pos,head) rows.
    const int n = n0 + tj;           // 4 cols, same head (tj % 4 == 0)
    const int head = n >> 5;
    const int d0 = n & 31;           // multiple of 4
    const int within = (d0 * 2) & 15;          // 0 or 8
    const int u_hi = d0 >> 3;                  // 0..3
    const int u_lo = 4 + (d0 >> 3);            // 4..7
#pragma unroll
    for (int i = 0; i < 4; i++) {
        const int m = m0 + ti + i;
        unsigned short hs[4], ls[4];
#pragma unroll
        for (int j = 0; j < 4; j++) {
            float f = acc[i][j];
            __nv_bfloat16 hb = __float2bfloat16(f);
            __nv_bfloat16 lb = __float2bfloat16(f - __bfloat162float(hb));
            hs[j] = __bfloat16_as_ushort(hb);
            ls[j] = __bfloat16_as_ushort(lb);
        }
        uint2 hv, lv;
        hv.x = (unsigned)hs[0] | ((unsigned)hs[1] << 16);
        hv.y = (unsigned)hs[2] | ((unsigned)hs[3] << 16);
        lv.x = (unsigned)ls[0] | ((unsigned)ls[1] << 16);
        lv.y = (unsigned)ls[2] | ((unsigned)ls[3] << 16);

        unsigned char* base = (unsigned char*)(isQ ? g_Q_sw : g_K_sw)
                            + (size_t)(m * 8 + head) * 128;
        const int r7 = m & 7;
        *(uint2*)(base + ((u_hi ^ r7) << 4) + within) = hv;
        *(uint2*)(base + ((u_lo ^ r7) << 4) + within) = lv;
    }
}

// ---------------------------------------------------------------------------
// Main kernel: warp-level mma.sync bf16-split. CTA 64k x 32q, 8 warps
// (4k x 2q grid), warp tile 16k x 16q over all 8 heads.
// ---------------------------------------------------------------------------
#define SM_K    0          // 64 rows * 1KB = 65536
#define SM_Q    65536      // 32 rows * 1KB = 32768
#define SM_RPE  98304      // 257 * 16B = 4112
#define SM_QP   102416     // 32 * 4B
#define SM_KP   102544     // 64 * 4B
#define SM_TOT  102800

#define LDSM4(r, addr) \
    asm volatile("ldmatrix.sync.aligned.m8n8.x4.shared.b16 {%0,%1,%2,%3}, [%4];" \
        : "=r"((r)[0]),"=r"((r)[1]),"=r"((r)[2]),"=r"((r)[3]) : "r"(addr))

#define MMA_BF16(accp, a, b0, b1) \
    asm volatile("mma.sync.aligned.m16n8k16.row.col.f32.bf16.bf16.f32 " \
        "{%0,%1,%2,%3}, {%4,%5,%6,%7}, {%8,%9}, {%0,%1,%2,%3};" \
        : "+f"((accp)[0]),"+f"((accp)[1]),"+f"((accp)[2]),"+f"((accp)[3]) \
        : "r"((a)[0]),"r"((a)[1]),"r"((a)[2]),"r"((a)[3]), "r"(b0),"r"(b1))

static __device__ __forceinline__ uint32_t smem_u32(const void* p) {
    uint32_t a;
    asm("{ .reg .u64 t; cvta.to.shared.u64 t, %1; cvt.u32.u64 %0, t; }"
        : "=r"(a) : "l"(p));
    return a;
}

__global__ __launch_bounds__(256) void rpe_gate_mma(
    const int*   __restrict__ qpos, const int* __restrict__ kpos,
    const float* __restrict__ rpe_table,
    const float* __restrict__ w1, const float* __restrict__ b1,
    const float* __restrict__ w2, const float* __restrict__ b2,
    float* __restrict__ out)
{
    extern __shared__ char sm[];
    const uint32_t sb = smem_u32(sm);

    const int tid  = threadIdx.x;
    const int wid  = tid >> 5;
    const int lane = tid & 31;
    const int ktile = blockIdx.x;   // 64 k rows
    const int qtile = blockIdx.y;   // 32 q cols

    // Stage K tile (64KB) + Q tile (32KB) via cp.async, layout-preserving.
    {
        const uint4* srcK = g_K_sw + (size_t)ktile * 4096;   // 64*8*8 units
        const uint4* srcQ = g_Q_sw + (size_t)qtile * 2048;   // 32*8*8 units
#pragma unroll
        for (int i = 0; i < 16; i++) {
            int u = tid + i * 256;
            asm volatile("cp.async.cg.shared.global [%0], [%1], 16;"
                :: "r"(sb + SM_K + u * 16), "l"(srcK + u) : "memory");
        }
#pragma unroll
        for (int i = 0; i < 8; i++) {
            int u = tid + i * 256;
            asm volatile("cp.async.cg.shared.global [%0], [%1], 16;"
                :: "r"(sb + SM_Q + u * 16), "l"(srcQ + u) : "memory");
        }
        asm volatile("cp.async.commit_group;");
    }
    // rpe + positions via normal loads
    for (int i = tid; i < 257; i += 256)
        *(float4*)(sm + SM_RPE + i * 16) = ((const float4*)rpe_table)[i];
    if (tid < 32) *(int*)(sm + SM_QP + tid * 4) = qpos[qtile * 32 + tid];
    if (tid < 64) *(int*)(sm + SM_KP + tid * 4) = kpos[ktile * 64 + tid];

    asm volatile("cp.async.wait_group 0;");
    __syncthreads();

    // warp layout: wk = wid&3 (k sub), wq = wid>>2 (q sub)
    const int wk0 = (wid & 3) * 16;
    const int wq0 = (wid >> 2) * 16;

    // ldmatrix thread address components
    const int rowA = wk0 + (lane & 7) + ((lane >> 3) & 1) * 8;  // A: g0 r0-7,u ; g1 r8-15,u ; g2 r0-7,u+1 ; g3 r8-15,u+1
    const int uaddA = (lane >> 4) & 1;
    const int rowB = wq0 + (lane & 7) + ((lane >> 4) & 1) * 8;  // B: g0 n0-7,u ; g1 n0-7,u+1 ; g2 n8-15,u ; g3 n8-15,u+1
    const int uaddB = (lane >> 3) & 1;
    const uint32_t aRow = sb + SM_K + rowA * 1024;
    const uint32_t bRow = sb + SM_Q + rowB * 1024;
    const int ar7 = rowA & 7;
    const int br7 = rowB & 7;

    float acc[8][2][4];
#pragma unroll
    for (int h = 0; h < 8; h++)
#pragma unroll
        for (int j = 0; j < 2; j++)
#pragma unroll
            for (int c = 0; c < 4; c++) acc[h][j][c] = 0.f;

#pragma unroll
    for (int h = 0; h < 8; h++) {
        const uint32_t ah = aRow + h * 128;
        const uint32_t bh = bRow + h * 128;
#pragma unroll
        for (int s = 0; s < 2; s++) {
            const int uHiA = s * 2 + uaddA, uLoA = uHiA + 4;
            const int uHiB = s * 2 + uaddB, uLoB = uHiB + 4;
            uint32_t aH[4], aL[4], bH[4], bL[4];
            LDSM4(aH, ah + ((uHiA ^ ar7) << 4));
            LDSM4(bH, bh + ((uHiB ^ br7) << 4));
            LDSM4(aL, ah + ((uLoA ^ ar7) << 4));
            LDSM4(bL, bh + ((uLoB ^ br7) << 4));
            MMA_BF16(acc[h][0], aH, bH[0], bH[1]);
            MMA_BF16(acc[h][1], aH, bH[2], bH[3]);
            MMA_BF16(acc[h][0], aH, bL[0], bL[1]);
            MMA_BF16(acc[h][1], aH, bL[2], bL[3]);
            MMA_BF16(acc[h][0], aL, bH[0], bH[1]);
            MMA_BF16(acc[h][1], aL, bH[2], bH[3]);
        }
    }

    // ---- Epilogue ----
    float w1r[8][4], b1r[8], w2r[4][8], b2r[4];
#pragma unroll
    for (int e = 0; e < 8; e++) {
        b1r[e] = __ldg(&b1[e]);
#pragma unroll
        for (int h = 0; h < 4; h++) w1r[e][h] = __ldg(&w1[e * 4 + h]);
    }
#pragma unroll
    for (int h = 0; h < 4; h++) {
        b2r[h] = __ldg(&b2[h]);
#pragma unroll
        for (int e = 0; e < 8; e++) w2r[h][e] = __ldg(&w2[h * 8 + e]);
    }

    const float4* rpe_s = (const float4*)(sm + SM_RPE);
    const int* qp_s = (const int*)(sm + SM_QP);
    const int* kp_s = (const int*)(sm + SM_KP);

    const int krow0 = wk0 + (lane >> 2);        // +0 / +8
    const int qcol0 = wq0 + (lane & 3) * 2;     // + j*8 + {0,1}
    const int kg0 = ktile * 64;
    const int qg0 = qtile * 32;

    int kv[2], qv[2][2];
#pragma unroll
    for (int kr = 0; kr < 2; kr++) kv[kr] = kp_s[krow0 + kr * 8];
#pragma unroll
    for (int j = 0; j < 2; j++)
#pragma unroll
        for (int qc = 0; qc < 2; qc++) qv[j][qc] = qp_s[qcol0 + j * 8 + qc];

#pragma unroll
    for (int j = 0; j < 2; j++) {
#pragma unroll
        for (int kr = 0; kr < 2; kr++) {
#pragma unroll
            for (int qc = 0; qc < 2; qc++) {
                const int c = kr * 2 + qc;
                int rel = qv[j][qc] - kv[kr];
                rel = rel < -128 ? -128 : (rel > 128 ? 128 : rel);
                float4 rp = rpe_s[rel + 128];
                float rph[4] = {rp.x, rp.y, rp.z, rp.w};

                float sh[4], gh[4];
#pragma unroll
                for (int h = 0; h < 4; h++) {
                    sh[h] = fmaxf(acc[h][j][c] + rph[h], 0.f);
                    gh[h] = acc[4 + h][j][c] + rph[h];
                }
                float zh[4] = {b2r[0], b2r[1], b2r[2], b2r[3]};
#pragma unroll
                for (int e = 0; e < 8; e++) {
                    float t = b1r[e];
#pragma unroll
                    for (int h = 0; h < 4; h++) t = fmaf(gh[h], w1r[e][h], t);
                    t = fmaxf(t, 0.f);
#pragma unroll
                    for (int h = 0; h < 4; h++) zh[h] = fmaf(t, w2r[h][e], zh[h]);
                }
                float o = 0.f;
#pragma unroll
                for (int h = 0; h < 4; h++) {
                    float g = __fdividef(1.f, 1.f + __expf(-zh[h]));
                    o = fmaf(sh[h], g, o);
                }
                const int qg = qg0 + qcol0 + j * 8 + qc;
                const int kg = kg0 + krow0 + kr * 8;
                out[(size_t)qg * NK + kg] = o;
            }
        }
    }
}

// ---------------------------------------------------------------------------
extern "C" void kernel_launch(void* const* d_in, const int* in_sizes, int n_in,
                              void* d_out, int out_size)
{
    const float* query = (const float*)d_in[0];
    const float* key   = (const float*)d_in[1];
    const int*   qpos  = (const int*)  d_in[2];
    const int*   kpos  = (const int*)  d_in[3];
    const float* Wq    = (const float*)d_in[4];
    const float* Wk    = (const float*)d_in[5];
    const float* rpe   = (const float*)d_in[6];
    const float* w1    = (const float*)d_in[7];
    const float* b1    = (const float*)d_in[8];
    const float* w2    = (const float*)d_in[9];
    const float* b2    = (const float*)d_in[10];
    float* out = (float*)d_out;
    (void)in_sizes; (void)n_in; (void)out_size;

    static int configured = 0;
    if (!configured) {
        cudaFuncSetAttribute(rpe_gate_mma,
                             cudaFuncAttributeMaxDynamicSharedMemorySize, SM_TOT);
        configured = 1;
    }

    proj_fused<<<384, 256>>>(query, key, Wq, Wk);
    rpe_gate_mma<<<dim3(NK / 64, NQ / 32), 256, SM_TOT>>>(
        qpos, kpos, rpe, w1, b1, w2, b2, out);
}

// round 7
// speedup vs baseline: 3.2970x; 1.6430x over previous
#include <cuda_runtime.h>
#include <cuda_bf16.h>
#include <cstdint>

#define NQ 2048
#define NK 4096
#define DIMK 1024

// Split-bf16 operand storage: per (pos, head) one 128B row = hi d0..31 | lo d0..31,
// 16B units permuted u ^= (pos & 7)  (conflict-free ldmatrix).
__device__ uint4 g_K_sw[NK * 8 * 8];   // (pos*8+head)*8 units
__device__ uint4 g_Q_sw[NQ * 8 * 8];

#define LDSM4(r, addr) \
    asm volatile("ldmatrix.sync.aligned.m8n8.x4.shared.b16 {%0,%1,%2,%3}, [%4];" \
        : "=r"((r)[0]),"=r"((r)[1]),"=r"((r)[2]),"=r"((r)[3]) : "r"(addr))

#define MMA_BF16(accp, a, b0, b1) \
    asm volatile("mma.sync.aligned.m16n8k16.row.col.f32.bf16.bf16.f32 " \
        "{%0,%1,%2,%3}, {%4,%5,%6,%7}, {%8,%9}, {%0,%1,%2,%3};" \
        : "+f"((accp)[0]),"+f"((accp)[1]),"+f"((accp)[2]),"+f"((accp)[3]) \
        : "r"((a)[0]),"r"((a)[1]),"r"((a)[2]),"r"((a)[3]), "r"(b0),"r"(b1))

static __device__ __forceinline__ uint32_t smem_u32(const void* p) {
    uint32_t a;
    asm("{ .reg .u64 t; cvta.to.shared.u64 t, %1; cvt.u32.u64 %0, t; }"
        : "=r"(a) : "l"(p));
    return a;
}

static __device__ __forceinline__ void split2(float f0, float f1,
                                              uint32_t& hv, uint32_t& lv) {
    __nv_bfloat16 h0 = __float2bfloat16(f0);
    __nv_bfloat16 h1 = __float2bfloat16(f1);
    __nv_bfloat16 l0 = __float2bfloat16(f0 - __bfloat162float(h0));
    __nv_bfloat16 l1 = __float2bfloat16(f1 - __bfloat162float(h1));
    hv = (uint32_t)__bfloat16_as_ushort(h0) | ((uint32_t)__bfloat16_as_ushort(h1) << 16);
    lv = (uint32_t)__bfloat16_as_ushort(l0) | ((uint32_t)__bfloat16_as_ushort(l1) << 16);
}

// ---------------------------------------------------------------------------
// Tensor-core projection: C[M,256] = A[M,1024] @ W[256,1024]^T, bf16-split.
// CTA 128M x 64N, 8 warps (4m x 2n), warp 32x32, K-chunk 32, double-buffered.
// Inputs converted fp32 -> bf16 hi|lo while staging; smem chunk layout is the
// same 128B hi|lo row + XOR-unit swizzle the main kernel uses.
// Grid: 48 m-tiles (16 Q + 32 K) x 4 n-tiles = 192 CTAs.
// ---------------------------------------------------------------------------
__global__ __launch_bounds__(256, 2) void proj_mma(
    const float* __restrict__ Qin, const float* __restrict__ Kin,
    const float* __restrict__ Wq,  const float* __restrict__ Wk)
{
    __shared__ char smA[2][16384];   // 128 rows x 128B (hi32|lo32 bf16)
    __shared__ char smW[2][8192];    // 64 rows x 128B

    const int mtile = blockIdx.x >> 2;
    const int ntile = blockIdx.x & 3;
    const float* A; int isQ, m0;
    if (mtile < 16) { A = Qin; isQ = 1; m0 = mtile * 128; }
    else            { A = Kin; isQ = 0; m0 = (mtile - 16) * 128; }
    const float* W = isQ ? Wq : Wk;
    const int n0 = ntile * 64;

    const int tid  = threadIdx.x;
    const int wid  = tid >> 5;
    const int lane = tid & 31;
    const int wm = wid >> 1;      // 0..3 -> m sub 32
    const int wn = wid & 1;       // 0..1 -> n sub 32

    // ---- load/convert thread mapping ----
    const int lrow = tid >> 3;        // 0..31 (+32 per pass)
    const int fc   = tid & 7;         // float4 col (d0 = fc*4)
    const float* aBase = A + (size_t)(m0 + lrow) * DIMK + fc * 4;
    const float* wBase = W + (size_t)(n0 + lrow) * DIMK + fc * 4;
    const int r7L  = lrow & 7;
    const int hiOff = (((fc >> 1) ^ r7L) << 4) + (fc & 1) * 8;
    const int loOff = ((((fc >> 1) + 4) ^ r7L) << 4) + (fc & 1) * 8;

    const uint32_t smA_u = smem_u32(smA);
    const uint32_t smW_u = smem_u32(smW);

    float4 pa[4], pw[2];
#pragma unroll
    for (int p = 0; p < 4; p++) pa[p] = *(const float4*)(aBase + p * 32 * DIMK);
#pragma unroll
    for (int p = 0; p < 2; p++) pw[p] = *(const float4*)(wBase + p * 32 * DIMK);

    // store chunk 0 into buf 0
#pragma unroll
    for (int p = 0; p < 4; p++) {
        uint32_t h0, l0, h1, l1;
        split2(pa[p].x, pa[p].y, h0, l0);
        split2(pa[p].z, pa[p].w, h1, l1);
        char* rb = smA[0] + (lrow + p * 32) * 128;
        *(uint2*)(rb + hiOff) = make_uint2(h0, h1);
        *(uint2*)(rb + loOff) = make_uint2(l0, l1);
    }
#pragma unroll
    for (int p = 0; p < 2; p++) {
        uint32_t h0, l0, h1, l1;
        split2(pw[p].x, pw[p].y, h0, l0);
        split2(pw[p].z, pw[p].w, h1, l1);
        char* rb = smW[0] + (lrow + p * 32) * 128;
        *(uint2*)(rb + hiOff) = make_uint2(h0, h1);
        *(uint2*)(rb + loOff) = make_uint2(l0, l1);
    }
    __syncthreads();

    // ---- ldmatrix per-thread address components ----
    const int rowA0 = wm * 32 + (lane & 7) + ((lane >> 3) & 1) * 8;  // mm adds +16
    const int uaddA = (lane >> 4) & 1;
    const int rowB0 = wn * 32 + (lane & 7) + ((lane >> 4) & 1) * 8;  // nsub adds +16
    const int uaddB = (lane >> 3) & 1;
    const int ar7_0 = rowA0 & 7;           // same for rowA0+16
    const int br7_0 = rowB0 & 7;

    float acc[2][4][4];
#pragma unroll
    for (int mm = 0; mm < 2; mm++)
#pragma unroll
        for (int nn = 0; nn < 4; nn++)
#pragma unroll
            for (int c = 0; c < 4; c++) acc[mm][nn][c] = 0.f;

    for (int ch = 0; ch < 32; ch++) {
        const int buf = ch & 1;
        if (ch < 31) {
            const int kc = (ch + 1) * 32;
#pragma unroll
            for (int p = 0; p < 4; p++) pa[p] = *(const float4*)(aBase + p * 32 * DIMK + kc);
#pragma unroll
            for (int p = 0; p < 2; p++) pw[p] = *(const float4*)(wBase + p * 32 * DIMK + kc);
        }

        const uint32_t aB = smA_u + buf * 16384;
        const uint32_t bB = smW_u + buf * 8192;
#pragma unroll
        for (int s = 0; s < 2; s++) {
            const int uHA = s * 2 + uaddA, uLA = uHA + 4;
            const int uHB = s * 2 + uaddB, uLB = uHB + 4;
            uint32_t aH0[4], aH1[4], aL0[4], aL1[4];
            uint32_t bH0[4], bH1[4], bL0[4], bL1[4];
            LDSM4(aH0, aB + rowA0 * 128        + ((uHA ^ ar7_0) << 4));
            LDSM4(aH1, aB + (rowA0 + 16) * 128 + ((uHA ^ ar7_0) << 4));
            LDSM4(bH0, bB + rowB0 * 128        + ((uHB ^ br7_0) << 4));
            LDSM4(bH1, bB + (rowB0 + 16) * 128 + ((uHB ^ br7_0) << 4));
            LDSM4(aL0, aB + rowA0 * 128        + ((uLA ^ ar7_0) << 4));
            LDSM4(aL1, aB + (rowA0 + 16) * 128 + ((uLA ^ ar7_0) << 4));
            LDSM4(bL0, bB + rowB0 * 128        + ((uLB ^ br7_0) << 4));
            LDSM4(bL1, bB + (rowB0 + 16) * 128 + ((uLB ^ br7_0) << 4));

            // hi*hi
            MMA_BF16(acc[0][0], aH0, bH0[0], bH0[1]); MMA_BF16(acc[0][1], aH0, bH0[2], bH0[3]);
            MMA_BF16(acc[0][2], aH0, bH1[0], bH1[1]); MMA_BF16(acc[0][3], aH0, bH1[2], bH1[3]);
            MMA_BF16(acc[1][0], aH1, bH0[0], bH0[1]); MMA_BF16(acc[1][1], aH1, bH0[2], bH0[3]);
            MMA_BF16(acc[1][2], aH1, bH1[0], bH1[1]); MMA_BF16(acc[1][3], aH1, bH1[2], bH1[3]);
            // hi*lo
            MMA_BF16(acc[0][0], aH0, bL0[0], bL0[1]); MMA_BF16(acc[0][1], aH0, bL0[2], bL0[3]);
            MMA_BF16(acc[0][2], aH0, bL1[0], bL1[1]); MMA_BF16(acc[0][3], aH0, bL1[2], bL1[3]);
            MMA_BF16(acc[1][0], aH1, bL0[0], bL0[1]); MMA_BF16(acc[1][1], aH1, bL0[2], bL0[3]);
            MMA_BF16(acc[1][2], aH1, bL1[0], bL1[1]); MMA_BF16(acc[1][3], aH1, bL1[2], bL1[3]);
            // lo*hi
            MMA_BF16(acc[0][0], aL0, bH0[0], bH0[1]); MMA_BF16(acc[0][1], aL0, bH0[2], bH0[3]);
            MMA_BF16(acc[0][2], aL0, bH1[0], bH1[1]); MMA_BF16(acc[0][3], aL0, bH1[2], bH1[3]);
            MMA_BF16(acc[1][0], aL1, bH0[0], bH0[1]); MMA_BF16(acc[1][1], aL1, bH0[2], bH0[3]);
            MMA_BF16(acc[1][2], aL1, bH1[0], bH1[1]); MMA_BF16(acc[1][3], aL1, bH1[2], bH1[3]);
        }
        __syncthreads();

        if (ch < 31) {
            const int nb = 1 - buf;
#pragma unroll
            for (int p = 0; p < 4; p++) {
                uint32_t h0, l0, h1, l1;
                split2(pa[p].x, pa[p].y, h0, l0);
                split2(pa[p].z, pa[p].w, h1, l1);
                char* rb = smA[nb] + (lrow + p * 32) * 128;
                *(uint2*)(rb + hiOff) = make_uint2(h0, h1);
                *(uint2*)(rb + loOff) = make_uint2(l0, l1);
            }
#pragma unroll
            for (int p = 0; p < 2; p++) {
                uint32_t h0, l0, h1, l1;
                split2(pw[p].x, pw[p].y, h0, l0);
                split2(pw[p].z, pw[p].w, h1, l1);
                char* rb = smW[nb] + (lrow + p * 32) * 128;
                *(uint2*)(rb + hiOff) = make_uint2(h0, h1);
                *(uint2*)(rb + loOff) = make_uint2(l0, l1);
            }
            __syncthreads();
        }
    }

    // ---- Epilogue: fp32 -> bf16 split, write swizzled global layout ----
    unsigned char* gbase = (unsigned char*)(isQ ? g_Q_sw : g_K_sw);
#pragma unroll
    for (int mm = 0; mm < 2; mm++) {
#pragma unroll
        for (int nn = 0; nn < 4; nn++) {
            const int n = n0 + wn * 32 + nn * 8 + (lane & 3) * 2;
            const int head = n >> 5;
            const int d0 = n & 31;
            const int u = d0 >> 3;
            const int within = (d0 & 7) * 2;
#pragma unroll
            for (int rr = 0; rr < 2; rr++) {
                const int m = m0 + wm * 32 + mm * 16 + (lane >> 2) + rr * 8;
                uint32_t hv, lv;
                split2(acc[mm][nn][rr * 2], acc[mm][nn][rr * 2 + 1], hv, lv);
                unsigned char* rb = gbase + (size_t)(m * 8 + head) * 128;
                const int r7 = m & 7;
                *(uint32_t*)(rb + ((u ^ r7) << 4) + within)       = hv;
                *(uint32_t*)(rb + (((u + 4) ^ r7) << 4) + within) = lv;
            }
        }
    }
}

// ---------------------------------------------------------------------------
// Main kernel (unchanged from R5): warp-level mma.sync bf16-split.
// CTA 64k x 32q, 8 warps, warp tile 16k x 16q over all 8 heads.
// ---------------------------------------------------------------------------
#define SM_K    0
#define SM_Q    65536
#define SM_RPE  98304
#define SM_QP   102416
#define SM_KP   102544
#define SM_TOT  102800

__global__ __launch_bounds__(256) void rpe_gate_mma(
    const int*   __restrict__ qpos, const int* __restrict__ kpos,
    const float* __restrict__ rpe_table,
    const float* __restrict__ w1, const float* __restrict__ b1,
    const float* __restrict__ w2, const float* __restrict__ b2,
    float* __restrict__ out)
{
    extern __shared__ char sm[];
    const uint32_t sb = smem_u32(sm);

    const int tid  = threadIdx.x;
    const int wid  = tid >> 5;
    const int lane = tid & 31;
    const int ktile = blockIdx.x;
    const int qtile = blockIdx.y;

    {
        const uint4* srcK = g_K_sw + (size_t)ktile * 4096;
        const uint4* srcQ = g_Q_sw + (size_t)qtile * 2048;
#pragma unroll
        for (int i = 0; i < 16; i++) {
            int u = tid + i * 256;
            asm volatile("cp.async.cg.shared.global [%0], [%1], 16;"
                :: "r"(sb + SM_K + u * 16), "l"(srcK + u) : "memory");
        }
#pragma unroll
        for (int i = 0; i < 8; i++) {
            int u = tid + i * 256;
            asm volatile("cp.async.cg.shared.global [%0], [%1], 16;"
                :: "r"(sb + SM_Q + u * 16), "l"(srcQ + u) : "memory");
        }
        asm volatile("cp.async.commit_group;");
    }
    for (int i = tid; i < 257; i += 256)
        *(float4*)(sm + SM_RPE + i * 16) = ((const float4*)rpe_table)[i];
    if (tid < 32) *(int*)(sm + SM_QP + tid * 4) = qpos[qtile * 32 + tid];
    if (tid < 64) *(int*)(sm + SM_KP + tid * 4) = kpos[ktile * 64 + tid];

    asm volatile("cp.async.wait_group 0;");
    __syncthreads();

    const int wk0 = (wid & 3) * 16;
    const int wq0 = (wid >> 2) * 16;

    const int rowA = wk0 + (lane & 7) + ((lane >> 3) & 1) * 8;
    const int uaddA = (lane >> 4) & 1;
    const int rowB = wq0 + (lane & 7) + ((lane >> 4) & 1) * 8;
    const int uaddB = (lane >> 3) & 1;
    const uint32_t aRow = sb + SM_K + rowA * 1024;
    const uint32_t bRow = sb + SM_Q + rowB * 1024;
    const int ar7 = rowA & 7;
    const int br7 = rowB & 7;

    float acc[8][2][4];
#pragma unroll
    for (int h = 0; h < 8; h++)
#pragma unroll
        for (int j = 0; j < 2; j++)
#pragma unroll
            for (int c = 0; c < 4; c++) acc[h][j][c] = 0.f;

#pragma unroll
    for (int h = 0; h < 8; h++) {
        const uint32_t ah = aRow + h * 128;
        const uint32_t bh = bRow + h * 128;
#pragma unroll
        for (int s = 0; s < 2; s++) {
            const int uHiA = s * 2 + uaddA, uLoA = uHiA + 4;
            const int uHiB = s * 2 + uaddB, uLoB = uHiB + 4;
            uint32_t aH[4], aL[4], bH[4], bL[4];
            LDSM4(aH, ah + ((uHiA ^ ar7) << 4));
            LDSM4(bH, bh + ((uHiB ^ br7) << 4));
            LDSM4(aL, ah + ((uLoA ^ ar7) << 4));
            LDSM4(bL, bh + ((uLoB ^ br7) << 4));
            MMA_BF16(acc[h][0], aH, bH[0], bH[1]);
            MMA_BF16(acc[h][1], aH, bH[2], bH[3]);
            MMA_BF16(acc[h][0], aH, bL[0], bL[1]);
            MMA_BF16(acc[h][1], aH, bL[2], bL[3]);
            MMA_BF16(acc[h][0], aL, bH[0], bH[1]);
            MMA_BF16(acc[h][1], aL, bH[2], bH[3]);
        }
    }

    float w1r[8][4], b1r[8], w2r[4][8], b2r[4];
#pragma unroll
    for (int e = 0; e < 8; e++) {
        b1r[e] = __ldg(&b1[e]);
#pragma unroll
        for (int h = 0; h < 4; h++) w1r[e][h] = __ldg(&w1[e * 4 + h]);
    }
#pragma unroll
    for (int h = 0; h < 4; h++) {
        b2r[h] = __ldg(&b2[h]);
#pragma unroll
        for (int e = 0; e < 8; e++) w2r[h][e] = __ldg(&w2[h * 8 + e]);
    }

    const float4* rpe_s = (const float4*)(sm + SM_RPE);
    const int* qp_s = (const int*)(sm + SM_QP);
    const int* kp_s = (const int*)(sm + SM_KP);

    const int krow0 = wk0 + (lane >> 2);
    const int qcol0 = wq0 + (lane & 3) * 2;
    const int kg0 = ktile * 64;
    const int qg0 = qtile * 32;

    int kv[2], qv[2][2];
#pragma unroll
    for (int kr = 0; kr < 2; kr++) kv[kr] = kp_s[krow0 + kr * 8];
#pragma unroll
    for (int j = 0; j < 2; j++)
#pragma unroll
        for (int qc = 0; qc < 2; qc++) qv[j][qc] = qp_s[qcol0 + j * 8 + qc];

#pragma unroll
    for (int j = 0; j < 2; j++) {
#pragma unroll
        for (int kr = 0; kr < 2; kr++) {
#pragma unroll
            for (int qc = 0; qc < 2; qc++) {
                const int c = kr * 2 + qc;
                int rel = qv[j][qc] - kv[kr];
                rel = rel < -128 ? -128 : (rel > 128 ? 128 : rel);
                float4 rp = rpe_s[rel + 128];
                float rph[4] = {rp.x, rp.y, rp.z, rp.w};

                float sh[4], gh[4];
#pragma unroll
                for (int h = 0; h < 4; h++) {
                    sh[h] = fmaxf(acc[h][j][c] + rph[h], 0.f);
                    gh[h] = acc[4 + h][j][c] + rph[h];
                }
                float zh[4] = {b2r[0], b2r[1], b2r[2], b2r[3]};
#pragma unroll
                for (int e = 0; e < 8; e++) {
                    float t = b1r[e];
#pragma unroll
                    for (int h = 0; h < 4; h++) t = fmaf(gh[h], w1r[e][h], t);
                    t = fmaxf(t, 0.f);
#pragma unroll
                    for (int h = 0; h < 4; h++) zh[h] = fmaf(t, w2r[h][e], zh[h]);
                }
                float o = 0.f;
#pragma unroll
                for (int h = 0; h < 4; h++) {
                    float g = __fdividef(1.f, 1.f + __expf(-zh[h]));
                    o = fmaf(sh[h], g, o);
                }
                const int qg = qg0 + qcol0 + j * 8 + qc;
                const int kg = kg0 + krow0 + kr * 8;
                out[(size_t)qg * NK + kg] = o;
            }
        }
    }
}

// ---------------------------------------------------------------------------
extern "C" void kernel_launch(void* const* d_in, const int* in_sizes, int n_in,
                              void* d_out, int out_size)
{
    const float* query = (const float*)d_in[0];
    const float* key   = (const float*)d_in[1];
    const int*   qpos  = (const int*)  d_in[2];
    const int*   kpos  = (const int*)  d_in[3];
    const float* Wq    = (const float*)d_in[4];
    const float* Wk    = (const float*)d_in[5];
    const float* rpe   = (const float*)d_in[6];
    const float* w1    = (const float*)d_in[7];
    const float* b1    = (const float*)d_in[8];
    const float* w2    = (const float*)d_in[9];
    const float* b2    = (const float*)d_in[10];
    float* out = (float*)d_out;
    (void)in_sizes; (void)n_in; (void)out_size;

    cudaFuncSetAttribute(rpe_gate_mma,
                         cudaFuncAttributeMaxDynamicSharedMemorySize, SM_TOT);

    proj_mma<<<192, 256>>>(query, key, Wq, Wk);
    rpe_gate_mma<<<dim3(NK / 64, NQ / 32), 256, SM_TOT>>>(
        qpos, kpos, rpe, w1, b1, w2, b2, out);
}